// round 16
// baseline (speedup 1.0000x reference)
#include <cuda_runtime.h>
#include <cuda_fp16.h>
#include <cstdint>

typedef unsigned long long u64;

#define Bn 256
#define Tn 256
#define Sn 20
#define NROWS (Bn*Tn)   // 65536

__device__ float g_zx[NROWS * 96];   // zx[row][96] = h_inner[row] @ Wo + bo
__device__ __align__(16) unsigned char g_btiles[32768];  // Bh|Bl fp16, swizzled

// ---------- packed f32x2 helpers (outer kernel) ----------
__device__ __forceinline__ u64 ffma2(u64 a, u64 b, u64 c){
    u64 d;
    asm("fma.rn.f32x2 %0, %1, %2, %3;" : "=l"(d) : "l"(a), "l"(b), "l"(c));
    return d;
}
__device__ __forceinline__ u64 add2(u64 a, u64 b){
    u64 d;
    asm("add.rn.f32x2 %0, %1, %2;" : "=l"(d) : "l"(a), "l"(b));
    return d;
}
__device__ __forceinline__ u64 pk2(float lo, float hi){
    u64 r; asm("mov.b64 %0, {%1, %2};" : "=l"(r) : "f"(lo), "f"(hi)); return r;
}
__device__ __forceinline__ void up2(u64 v, float& lo, float& hi){
    asm("mov.b64 {%0, %1}, %2;" : "=f"(lo), "=f"(hi) : "l"(v));
}

// ---------- activations ----------
__device__ __forceinline__ float tanha(float x){
    float r; asm("tanh.approx.f32 %0, %1;" : "=f"(r) : "f"(x)); return r;
}
__device__ __forceinline__ float sigt(float x){
    return fmaf(0.5f, tanha(0.5f * x), 0.5f);
}

// ---------- smem / swizzle ----------
__device__ __forceinline__ uint32_t smem_to_u32(const void* p){
    uint32_t a;
    asm("{ .reg .u64 t; cvta.to.shared.u64 t, %1; cvt.u32.u64 %0, t; }"
        : "=r"(a) : "l"(p));
    return a;
}
#define SWZ(bo) ((bo) ^ (((bo) >> 3) & 0x70))

// ---------- mma.sync / ldmatrix (fp16, baseline PTX) ----------
#define MMA_F16(d, a, b0v, b1v) \
    asm volatile("mma.sync.aligned.m16n8k16.row.col.f32.f16.f16.f32 " \
        "{%0,%1,%2,%3}, {%4,%5,%6,%7}, {%8,%9}, {%0,%1,%2,%3};" \
        : "+f"((d)[0]), "+f"((d)[1]), "+f"((d)[2]), "+f"((d)[3]) \
        : "r"((a)[0]), "r"((a)[1]), "r"((a)[2]), "r"((a)[3]), "r"(b0v), "r"(b1v))

#define LDSM4(r, addr) \
    asm volatile("ldmatrix.sync.aligned.m8n8.x4.shared.b16 {%0,%1,%2,%3}, [%4];" \
        : "=r"((r)[0]), "=r"((r)[1]), "=r"((r)[2]), "=r"((r)[3]) : "r"(addr))

// SMEM layout (bytes)
#define OFF_AH 0        // A hi [64 rows][64 cols] fp16, 8KB (cols 0..31 = h)
#define OFF_AL 8192     // A lo, 8KB
#define OFF_BH 16384    // B hi [128][64] fp16, 16KB (Wo fp32 reused post-loop)
#define OFF_BL 32768    // B lo, 16KB
#define OFF_BO 49152    // bo, 96 f32 (384B)
#define OFF_WB 49536    // per-unit (w4,b4) Wi/bi table: 32 units x 32B = 1KB
#define OFF_XS 50560    // x staged [s][row]: 20 x 64 f32 = 5120B
#define SMEM_SZ 55680

// =====================================================================
// B-tile prep: loop-invariant weight tiles (fp16 hi/lo, SW128-swizzled).
// =====================================================================
__global__ void bprep(const float* __restrict__ Wi,
                      const float* __restrict__ Ui,
                      const float* __restrict__ bi)
{
    int idx = blockIdx.x * 256 + threadIdx.x;
    if (idx >= 8192) return;
    int n = idx >> 6, k = idx & 63;
    int u, g;
    if (n < 64){ u = n >> 1; g = n & 1; }
    else       { u = (n - 64) >> 1; g = 2 + (n & 1); }
    int col = g * 32 + u;
    float w = (k < 32) ? Ui[k * 128 + col] : 0.f;
    __half wh = __float2half(w);
    __half wl = __float2half(w - __half2float(wh));
    uint32_t off = SWZ((uint32_t)(n * 128 + k * 2));
    *(__half*)(g_btiles + off)         = wh;
    *(__half*)(g_btiles + 16384 + off) = wl;
}

// =====================================================================
// Inner LSTM via warp-level fp16 mma.sync (R14 version, ~83us, UNCHANGED).
// =====================================================================
__global__ void __launch_bounds__(128, 4) inner_mma(
    const float* __restrict__ x,  const float* __restrict__ Wi,
    const float* __restrict__ bi,
    const float* __restrict__ Wo, const float* __restrict__ bo)
{
    extern __shared__ char smc[];
    const uint32_t sb = smem_to_u32(smc);
    const int tid  = threadIdx.x;
    const int wid  = tid >> 5;
    const int lane = tid & 31;
    const int q    = lane & 3;
    const int rr   = lane >> 2;
    const int wrow0 = wid * 16;

    {
        const uint4* src = (const uint4*)g_btiles;
        uint4* dst = (uint4*)(smc + OFF_BH);
        for (int i = tid; i < 2048; i += 128) dst[i] = src[i];
    }
    for (int i = tid; i < 4096; i += 128)
        ((uint32_t*)(smc + OFF_AH))[i] = 0u;
    if (tid < 96) ((float*)(smc + OFF_BO))[tid] = bo[tid];
    if (tid < 32){
        int u = tid;
        float4 w4 = make_float4(Wi[u], Wi[32 + u], Wi[64 + u], Wi[96 + u]);
        float4 b4 = make_float4(bi[u], bi[32 + u], bi[64 + u], bi[96 + u]);
        *(float4*)(smc + OFF_WB + u * 32)      = w4;
        *(float4*)(smc + OFF_WB + u * 32 + 16) = b4;
    }
    {
        const float* xg = x + (size_t)blockIdx.x * 64 * Sn;
        float* xsm = (float*)(smc + OFF_XS);
        for (int idx = tid; idx < 64 * Sn; idx += 128){
            int row = idx / Sn, s = idx % Sn;
            xsm[s * 64 + row] = xg[idx];
        }
    }
    __syncthreads();

    const uint32_t aRow  = wrow0 + (lane & 15);
    const uint32_t aByte = (uint32_t)(lane >> 4) << 4;
    const uint32_t aMask = (aRow & 7) << 4;
    const uint32_t aBase = sb + OFF_AH + aRow * 128;
    uint32_t akOff[2];
    #pragma unroll
    for (int kc = 0; kc < 2; kc++)
        akOff[kc] = (aByte + 32u * kc) ^ aMask;

    uint32_t bBase[8];
    uint32_t bkOff[2];
    {
        uint32_t nrow = ((uint32_t)(lane >> 4) << 3) + (lane & 7);
        uint32_t bbyte = ((uint32_t)((lane >> 3) & 1)) << 4;
        uint32_t bMask = (nrow & 7) << 4;
        #pragma unroll
        for (int np = 0; np < 8; np++)
            bBase[np] = sb + OFF_BH + (16 * np + nrow) * 128;
        #pragma unroll
        for (int kc = 0; kc < 2; kc++)
            bkOff[kc] = (bbyte + 32u * kc) ^ bMask;
    }

    float cst[16];
    #pragma unroll
    for (int i = 0; i < 16; i++) cst[i] = 0.f;

    const int row0 = wrow0 + rr;
    const int row1 = row0 + 8;
    const float* xsm = (const float*)(smc + OFF_XS);

    #pragma unroll 1
    for (int s = 0; s < Sn; s++){
        float x0 = xsm[s * 64 + row0];
        float x1 = xsm[s * 64 + row1];

        uint32_t ah[2][4], al[2][4];
        #pragma unroll
        for (int kc = 0; kc < 2; kc++){
            LDSM4(ah[kc], aBase + akOff[kc]);
            LDSM4(al[kc], aBase + 8192 + akOff[kc]);
        }
        __syncwarp();

        #pragma unroll
        for (int npp = 0; npp < 4; npp++){
            const int vA = 8 * npp + q;
            const int vB = vA + 4;
            float4 wA = *(const float4*)(smc + OFF_WB + vA * 32);
            float4 bA = *(const float4*)(smc + OFF_WB + vA * 32 + 16);
            float4 wB = *(const float4*)(smc + OFF_WB + vB * 32);
            float4 bB = *(const float4*)(smc + OFF_WB + vB * 32 + 16);
            float dIF0[4] = { fmaf(x0, wA.x, bA.x), fmaf(x0, wA.y, bA.y),
                              fmaf(x1, wA.x, bA.x), fmaf(x1, wA.y, bA.y) };
            float dGO0[4] = { fmaf(x0, wA.z, bA.z), fmaf(x0, wA.w, bA.w),
                              fmaf(x1, wA.z, bA.z), fmaf(x1, wA.w, bA.w) };
            float dIF1[4] = { fmaf(x0, wB.x, bB.x), fmaf(x0, wB.y, bB.y),
                              fmaf(x1, wB.x, bB.x), fmaf(x1, wB.y, bB.y) };
            float dGO1[4] = { fmaf(x0, wB.z, bB.z), fmaf(x0, wB.w, bB.w),
                              fmaf(x1, wB.z, bB.z), fmaf(x1, wB.w, bB.w) };
            #pragma unroll
            for (int kc = 0; kc < 2; kc++){
                uint32_t bIFh[4], bIFl[4], bGOh[4], bGOl[4];
                LDSM4(bIFh, bBase[npp]     + bkOff[kc]);
                LDSM4(bIFl, bBase[npp]     + 16384 + bkOff[kc]);
                LDSM4(bGOh, bBase[npp + 4] + bkOff[kc]);
                LDSM4(bGOl, bBase[npp + 4] + 16384 + bkOff[kc]);
                MMA_F16(dIF0, ah[kc], bIFh[0], bIFh[1]);
                MMA_F16(dIF0, ah[kc], bIFl[0], bIFl[1]);
                MMA_F16(dIF0, al[kc], bIFh[0], bIFh[1]);
                MMA_F16(dIF1, ah[kc], bIFh[2], bIFh[3]);
                MMA_F16(dIF1, ah[kc], bIFl[2], bIFl[3]);
                MMA_F16(dIF1, al[kc], bIFh[2], bIFh[3]);
                MMA_F16(dGO0, ah[kc], bGOh[0], bGOh[1]);
                MMA_F16(dGO0, ah[kc], bGOl[0], bGOl[1]);
                MMA_F16(dGO0, al[kc], bGOh[0], bGOh[1]);
                MMA_F16(dGO1, ah[kc], bGOh[2], bGOh[3]);
                MMA_F16(dGO1, ah[kc], bGOl[2], bGOl[3]);
                MMA_F16(dGO1, al[kc], bGOh[2], bGOh[3]);
            }
            #pragma unroll
            for (int e = 0; e < 4; e++){
                const float* dif = (e < 2) ? dIF0 : dIF1;
                const float* dgo = (e < 2) ? dGO0 : dGO1;
                int half_ = (e & 1) * 2;
                float zi = dif[half_], zf = dif[half_ + 1];
                float zg = dgo[half_], zo = dgo[half_ + 1];
                float ii = sigt(zi), ff = sigt(zf);
                float gg = tanha(zg), oo = sigt(zo);
                float cv = ff * cst[npp * 4 + e] + ii * gg;
                cst[npp * 4 + e] = cv;
                float h = oo * tanha(cv);
                int v  = (e < 2) ? vA : vB;
                int rw = (e & 1) ? row1 : row0;
                uint32_t off = SWZ((uint32_t)(rw * 128 + v * 2));
                __half hh = __float2half(h);
                __half hl = __float2half(h - __half2float(hh));
                *(__half*)(smc + OFF_AH + off) = hh;
                *(__half*)(smc + OFF_AL + off) = hl;
            }
        }
        __syncwarp();
    }

    // --- zx epilogue ---
    __syncthreads();
    {
        float4* dst = (float4*)(smc + OFF_BH);
        const float4* src = (const float4*)Wo;
        for (int i = tid; i < 768; i += 128) dst[i] = src[i];
    }
    __syncthreads();
    {
        const int row = tid >> 1;
        const int cg  = tid & 1;
        const float* wos = (float*)(smc + OFF_BH);
        const float* bos = (float*)(smc + OFF_BO);
        float4 acc[12];
        #pragma unroll
        for (int j = 0; j < 12; j++)
            acc[j] = *(const float4*)(bos + cg * 48 + j * 4);
        #pragma unroll 4
        for (int k = 0; k < 32; k++){
            uint32_t off = SWZ((uint32_t)(row * 128 + k * 2));
            float hk = __half2float(*(__half*)(smc + OFF_AH + off))
                     + __half2float(*(__half*)(smc + OFF_AL + off));
            const float4* wp = (const float4*)(wos + k * 96 + cg * 48);
            #pragma unroll
            for (int j = 0; j < 12; j++){
                float4 w = wp[j];
                acc[j].x = fmaf(hk, w.x, acc[j].x);
                acc[j].y = fmaf(hk, w.y, acc[j].y);
                acc[j].z = fmaf(hk, w.z, acc[j].z);
                acc[j].w = fmaf(hk, w.w, acc[j].w);
            }
        }
        float* zp = g_zx + ((size_t)blockIdx.x * 64 + row) * 96 + cg * 48;
        #pragma unroll
        for (int j = 0; j < 12; j++) *(float4*)(zp + j * 4) = acc[j];
    }
}

// =====================================================================
// Outer LSTM + dense head: TWO warps per batch row (k-split GEMV).
// Warp w computes partials over k in [12w, 12w+12): 24 ffma2/lane/step
// (vs 48). Warp1 is stateless: partials -> SMEM -> warp0 combines,
// does activations, broadcasts h (duplicated (h,h)) to both warps.
// Two __syncthreads per step (64-thread block).
// =====================================================================
__global__ void __launch_bounds__(64) outer_kernel(
    const int*   __restrict__ lengths,
    const float* __restrict__ Uo,
    const float* __restrict__ Wd,
    const float* __restrict__ bd,
    float*       __restrict__ out)
{
    __shared__ __align__(16) u64 hsm[2][24];
    __shared__ __align__(16) ulonglong2 psm[32];

    const int tid = threadIdx.x;
    const int w   = tid >> 5;              // 0 or 1
    const int l   = tid & 31;
    const int la  = (l < 24) ? l : 0;
    const int b   = blockIdx.x;

    // this warp's k-half weights (k = 12w + j)
    u64 w_if[12], w_go[12];
    #pragma unroll
    for (int j = 0; j < 12; j++){
        const float* row = Uo + (12 * w + j) * 96;
        w_if[j] = pk2(__ldg(row + la),      __ldg(row + 24 + la));
        w_go[j] = pk2(__ldg(row + 48 + la), __ldg(row + 72 + la));
    }

    const int len = lengths[b];            // in [1, T]
    const float* zr = g_zx + (size_t)b * Tn * 96;
    const bool isW0 = (w == 0);

    // both warps prefetch (same addresses; L2/L1 hit for the duplicate)
    u64 A0, B0, A1, B1;
    A0 = pk2(zr[la], zr[24 + la]);
    B0 = pk2(zr[48 + la], zr[72 + la]);
    {
        const float* z1 = zr + ((len > 1) ? 96 : 0);
        A1 = pk2(z1[la], z1[24 + la]);
        B1 = pk2(z1[48 + la], z1[72 + la]);
    }

    if (tid < 24) hsm[0][tid] = 0ULL;
    __syncthreads();

    float h = 0.f, c = 0.f;                // live only in warp 0
    const u64 Z = 0ULL;
    int t = 0;
    while (t < len){
        #pragma unroll
        for (int sub = 0; sub < 2; sub++){
            // z injected only in warp0's partial
            u64 zA, zB;
            if (sub == 0){
                zA = isW0 ? A0 : Z;  zB = isW0 ? B0 : Z;
                int tp = (t + 2 < len) ? t + 2 : len - 1;
                const float* zq = zr + (size_t)tp * 96;
                A0 = pk2(zq[la], zq[24 + la]); B0 = pk2(zq[48 + la], zq[72 + la]);
            } else {
                zA = isW0 ? A1 : Z;  zB = isW0 ? B1 : Z;
                int tp = (t + 2 < len) ? t + 2 : len - 1;
                const float* zq = zr + (size_t)tp * 96;
                A1 = pk2(zq[la], zq[24 + la]); B1 = pk2(zq[48 + la], zq[72 + la]);
            }
            const ulonglong2* hp2 =
                (const ulonglong2*)(hsm[sub]) + 6 * w;   // h[12w..12w+11]
            u64 a0 = zA, a1 = Z, b0 = zB, b1 = Z;
            #pragma unroll
            for (int j = 0; j < 3; j++){
                ulonglong2 p  = hp2[j];        // k=12w+2j, 12w+2j+1
                ulonglong2 qq = hp2[j + 3];    // k=12w+6+2j, +1
                a0 = ffma2(p.x,  w_if[2*j],     a0);
                b0 = ffma2(p.x,  w_go[2*j],     b0);
                a0 = ffma2(p.y,  w_if[2*j + 1], a0);
                b0 = ffma2(p.y,  w_go[2*j + 1], b0);
                a1 = ffma2(qq.x, w_if[6 + 2*j], a1);
                b1 = ffma2(qq.x, w_go[6 + 2*j], b1);
                a1 = ffma2(qq.y, w_if[7 + 2*j], a1);
                b1 = ffma2(qq.y, w_go[7 + 2*j], b1);
            }
            u64 pA = add2(a0, a1), pB = add2(b0, b1);
            if (!isW0){ ulonglong2 v; v.x = pA; v.y = pB; psm[l] = v; }
            __syncthreads();
            if (isW0){
                ulonglong2 pp = psm[l];
                u64 zAf = add2(pA, pp.x);
                u64 zBf = add2(pB, pp.y);
                float zi, zf, zg, zo;
                up2(zAf, zi, zf);
                up2(zBf, zg, zo);
                float fi = sigt(zi), ff = sigt(zf);
                float gg = tanha(zg), oo = sigt(zo);
                c = fmaf(ff, c, fi * gg);
                h = oo * tanha(c);
                if (l < 24) hsm[sub ^ 1][l] = pk2(h, h);
            }
            __syncthreads();
            if (++t >= len) break;
        }
    }

    // dense sigmoid head (warp 0 only)
    if (isW0){
        float p = (l < 24) ? h * __ldg(Wd + la) : 0.f;
        #pragma unroll
        for (int off = 16; off; off >>= 1)
            p += __shfl_xor_sync(0xffffffffu, p, off);
        if (l == 0) out[b] = fmaf(0.5f, tanha(0.5f * (p + bd[0])), 0.5f);
    }
}

extern "C" void kernel_launch(void* const* d_in, const int* in_sizes, int n_in,
                              void* d_out, int out_size)
{
    const float* x       = (const float*)d_in[0];
    const int*   lengths = (const int*)  d_in[1];
    const float* Wi      = (const float*)d_in[2];
    const float* Ui      = (const float*)d_in[3];
    const float* bi      = (const float*)d_in[4];
    const float* Wo      = (const float*)d_in[5];
    const float* Uo      = (const float*)d_in[6];
    const float* bo      = (const float*)d_in[7];
    const float* Wd      = (const float*)d_in[8];
    const float* bd      = (const float*)d_in[9];
    float* out = (float*)d_out;

    cudaFuncSetAttribute(inner_mma,
                         cudaFuncAttributeMaxDynamicSharedMemorySize, SMEM_SZ);

    bprep<<<32, 256>>>(Wi, Ui, bi);
    inner_mma<<<1024, 128, SMEM_SZ>>>(x, Wi, bi, Wo, bo);
    outer_kernel<<<256, 64>>>(lengths, Uo, Wd, bd, out);
}

// round 17
// speedup vs baseline: 1.1001x; 1.1001x over previous
#include <cuda_runtime.h>
#include <cuda_fp16.h>
#include <cstdint>

typedef unsigned long long u64;

#define Bn 256
#define Tn 256
#define Sn 20
#define NROWS (Bn*Tn)   // 65536

__device__ float g_zx[NROWS * 96];   // zx[row][96] = h_inner[row] @ Wo + bo
__device__ __align__(16) unsigned char g_btiles[32768];  // Bh|Bl fp16, swizzled

// ---------- activations ----------
__device__ __forceinline__ float tanha(float x){
    float r; asm("tanh.approx.f32 %0, %1;" : "=f"(r) : "f"(x)); return r;
}
__device__ __forceinline__ float sigt(float x){
    return fmaf(0.5f, tanha(0.5f * x), 0.5f);
}

// ---------- smem / swizzle ----------
__device__ __forceinline__ uint32_t smem_to_u32(const void* p){
    uint32_t a;
    asm("{ .reg .u64 t; cvta.to.shared.u64 t, %1; cvt.u32.u64 %0, t; }"
        : "=r"(a) : "l"(p));
    return a;
}
#define SWZ(bo) ((bo) ^ (((bo) >> 3) & 0x70))

// ---------- mma.sync / ldmatrix (fp16, baseline PTX) ----------
#define MMA_F16(d, a, b0v, b1v) \
    asm volatile("mma.sync.aligned.m16n8k16.row.col.f32.f16.f16.f32 " \
        "{%0,%1,%2,%3}, {%4,%5,%6,%7}, {%8,%9}, {%0,%1,%2,%3};" \
        : "+f"((d)[0]), "+f"((d)[1]), "+f"((d)[2]), "+f"((d)[3]) \
        : "r"((a)[0]), "r"((a)[1]), "r"((a)[2]), "r"((a)[3]), "r"(b0v), "r"(b1v))

#define LDSM4(r, addr) \
    asm volatile("ldmatrix.sync.aligned.m8n8.x4.shared.b16 {%0,%1,%2,%3}, [%4];" \
        : "=r"((r)[0]), "=r"((r)[1]), "=r"((r)[2]), "=r"((r)[3]) : "r"(addr))

// SMEM layout (bytes)
#define OFF_AH 0        // A hi [64 rows][64 cols] fp16, 8KB (cols 0..31 = h)
#define OFF_AL 8192     // A lo, 8KB
#define OFF_BH 16384    // B hi [128][64] fp16, 16KB (Wo fp32 reused post-loop)
#define OFF_BL 32768    // B lo, 16KB
#define OFF_BO 49152    // bo, 96 f32 (384B)
#define OFF_WB 49536    // per-unit (w4,b4) Wi/bi table: 32 units x 32B = 1KB
#define OFF_XS 50560    // x staged [s][row]: 20 x 64 f32 = 5120B
#define SMEM_SZ 55680

// =====================================================================
// B-tile prep: loop-invariant weight tiles (fp16 hi/lo, SW128-swizzled).
// =====================================================================
__global__ void bprep(const float* __restrict__ Wi,
                      const float* __restrict__ Ui,
                      const float* __restrict__ bi)
{
    int idx = blockIdx.x * 256 + threadIdx.x;
    if (idx >= 8192) return;
    int n = idx >> 6, k = idx & 63;
    int u, g;
    if (n < 64){ u = n >> 1; g = n & 1; }
    else       { u = (n - 64) >> 1; g = 2 + (n & 1); }
    int col = g * 32 + u;
    float w = (k < 32) ? Ui[k * 128 + col] : 0.f;
    __half wh = __float2half(w);
    __half wl = __float2half(w - __half2float(wh));
    uint32_t off = SWZ((uint32_t)(n * 128 + k * 2));
    *(__half*)(g_btiles + off)         = wh;
    *(__half*)(g_btiles + 16384 + off) = wl;
}

// =====================================================================
// Inner LSTM via warp-level fp16 mma.sync (R14 version, ~83us, UNCHANGED).
// =====================================================================
__global__ void __launch_bounds__(128, 4) inner_mma(
    const float* __restrict__ x,  const float* __restrict__ Wi,
    const float* __restrict__ bi,
    const float* __restrict__ Wo, const float* __restrict__ bo)
{
    extern __shared__ char smc[];
    const uint32_t sb = smem_to_u32(smc);
    const int tid  = threadIdx.x;
    const int wid  = tid >> 5;
    const int lane = tid & 31;
    const int q    = lane & 3;
    const int rr   = lane >> 2;
    const int wrow0 = wid * 16;

    {
        const uint4* src = (const uint4*)g_btiles;
        uint4* dst = (uint4*)(smc + OFF_BH);
        for (int i = tid; i < 2048; i += 128) dst[i] = src[i];
    }
    for (int i = tid; i < 4096; i += 128)
        ((uint32_t*)(smc + OFF_AH))[i] = 0u;
    if (tid < 96) ((float*)(smc + OFF_BO))[tid] = bo[tid];
    if (tid < 32){
        int u = tid;
        float4 w4 = make_float4(Wi[u], Wi[32 + u], Wi[64 + u], Wi[96 + u]);
        float4 b4 = make_float4(bi[u], bi[32 + u], bi[64 + u], bi[96 + u]);
        *(float4*)(smc + OFF_WB + u * 32)      = w4;
        *(float4*)(smc + OFF_WB + u * 32 + 16) = b4;
    }
    {
        const float* xg = x + (size_t)blockIdx.x * 64 * Sn;
        float* xsm = (float*)(smc + OFF_XS);
        for (int idx = tid; idx < 64 * Sn; idx += 128){
            int row = idx / Sn, s = idx % Sn;
            xsm[s * 64 + row] = xg[idx];
        }
    }
    __syncthreads();

    const uint32_t aRow  = wrow0 + (lane & 15);
    const uint32_t aByte = (uint32_t)(lane >> 4) << 4;
    const uint32_t aMask = (aRow & 7) << 4;
    const uint32_t aBase = sb + OFF_AH + aRow * 128;
    uint32_t akOff[2];
    #pragma unroll
    for (int kc = 0; kc < 2; kc++)
        akOff[kc] = (aByte + 32u * kc) ^ aMask;

    uint32_t bBase[8];
    uint32_t bkOff[2];
    {
        uint32_t nrow = ((uint32_t)(lane >> 4) << 3) + (lane & 7);
        uint32_t bbyte = ((uint32_t)((lane >> 3) & 1)) << 4;
        uint32_t bMask = (nrow & 7) << 4;
        #pragma unroll
        for (int np = 0; np < 8; np++)
            bBase[np] = sb + OFF_BH + (16 * np + nrow) * 128;
        #pragma unroll
        for (int kc = 0; kc < 2; kc++)
            bkOff[kc] = (bbyte + 32u * kc) ^ bMask;
    }

    float cst[16];
    #pragma unroll
    for (int i = 0; i < 16; i++) cst[i] = 0.f;

    const int row0 = wrow0 + rr;
    const int row1 = row0 + 8;
    const float* xsm = (const float*)(smc + OFF_XS);

    #pragma unroll 1
    for (int s = 0; s < Sn; s++){
        float x0 = xsm[s * 64 + row0];
        float x1 = xsm[s * 64 + row1];

        uint32_t ah[2][4], al[2][4];
        #pragma unroll
        for (int kc = 0; kc < 2; kc++){
            LDSM4(ah[kc], aBase + akOff[kc]);
            LDSM4(al[kc], aBase + 8192 + akOff[kc]);
        }
        __syncwarp();

        #pragma unroll
        for (int npp = 0; npp < 4; npp++){
            const int vA = 8 * npp + q;
            const int vB = vA + 4;
            float4 wA = *(const float4*)(smc + OFF_WB + vA * 32);
            float4 bA = *(const float4*)(smc + OFF_WB + vA * 32 + 16);
            float4 wB = *(const float4*)(smc + OFF_WB + vB * 32);
            float4 bB = *(const float4*)(smc + OFF_WB + vB * 32 + 16);
            float dIF0[4] = { fmaf(x0, wA.x, bA.x), fmaf(x0, wA.y, bA.y),
                              fmaf(x1, wA.x, bA.x), fmaf(x1, wA.y, bA.y) };
            float dGO0[4] = { fmaf(x0, wA.z, bA.z), fmaf(x0, wA.w, bA.w),
                              fmaf(x1, wA.z, bA.z), fmaf(x1, wA.w, bA.w) };
            float dIF1[4] = { fmaf(x0, wB.x, bB.x), fmaf(x0, wB.y, bB.y),
                              fmaf(x1, wB.x, bB.x), fmaf(x1, wB.y, bB.y) };
            float dGO1[4] = { fmaf(x0, wB.z, bB.z), fmaf(x0, wB.w, bB.w),
                              fmaf(x1, wB.z, bB.z), fmaf(x1, wB.w, bB.w) };
            #pragma unroll
            for (int kc = 0; kc < 2; kc++){
                uint32_t bIFh[4], bIFl[4], bGOh[4], bGOl[4];
                LDSM4(bIFh, bBase[npp]     + bkOff[kc]);
                LDSM4(bIFl, bBase[npp]     + 16384 + bkOff[kc]);
                LDSM4(bGOh, bBase[npp + 4] + bkOff[kc]);
                LDSM4(bGOl, bBase[npp + 4] + 16384 + bkOff[kc]);
                MMA_F16(dIF0, ah[kc], bIFh[0], bIFh[1]);
                MMA_F16(dIF0, ah[kc], bIFl[0], bIFl[1]);
                MMA_F16(dIF0, al[kc], bIFh[0], bIFh[1]);
                MMA_F16(dIF1, ah[kc], bIFh[2], bIFh[3]);
                MMA_F16(dIF1, ah[kc], bIFl[2], bIFl[3]);
                MMA_F16(dIF1, al[kc], bIFh[2], bIFh[3]);
                MMA_F16(dGO0, ah[kc], bGOh[0], bGOh[1]);
                MMA_F16(dGO0, ah[kc], bGOl[0], bGOl[1]);
                MMA_F16(dGO0, al[kc], bGOh[0], bGOh[1]);
                MMA_F16(dGO1, ah[kc], bGOh[2], bGOh[3]);
                MMA_F16(dGO1, ah[kc], bGOl[2], bGOl[3]);
                MMA_F16(dGO1, al[kc], bGOh[2], bGOh[3]);
            }
            #pragma unroll
            for (int e = 0; e < 4; e++){
                const float* dif = (e < 2) ? dIF0 : dIF1;
                const float* dgo = (e < 2) ? dGO0 : dGO1;
                int half_ = (e & 1) * 2;
                float zi = dif[half_], zf = dif[half_ + 1];
                float zg = dgo[half_], zo = dgo[half_ + 1];
                float ii = sigt(zi), ff = sigt(zf);
                float gg = tanha(zg), oo = sigt(zo);
                float cv = ff * cst[npp * 4 + e] + ii * gg;
                cst[npp * 4 + e] = cv;
                float h = oo * tanha(cv);
                int v  = (e < 2) ? vA : vB;
                int rw = (e & 1) ? row1 : row0;
                uint32_t off = SWZ((uint32_t)(rw * 128 + v * 2));
                __half hh = __float2half(h);
                __half hl = __float2half(h - __half2float(hh));
                *(__half*)(smc + OFF_AH + off) = hh;
                *(__half*)(smc + OFF_AL + off) = hl;
            }
        }
        __syncwarp();
    }

    // --- zx epilogue ---
    __syncthreads();
    {
        float4* dst = (float4*)(smc + OFF_BH);
        const float4* src = (const float4*)Wo;
        for (int i = tid; i < 768; i += 128) dst[i] = src[i];
    }
    __syncthreads();
    {
        const int row = tid >> 1;
        const int cg  = tid & 1;
        const float* wos = (float*)(smc + OFF_BH);
        const float* bos = (float*)(smc + OFF_BO);
        float4 acc[12];
        #pragma unroll
        for (int j = 0; j < 12; j++)
            acc[j] = *(const float4*)(bos + cg * 48 + j * 4);
        #pragma unroll 4
        for (int k = 0; k < 32; k++){
            uint32_t off = SWZ((uint32_t)(row * 128 + k * 2));
            float hk = __half2float(*(__half*)(smc + OFF_AH + off))
                     + __half2float(*(__half*)(smc + OFF_AL + off));
            const float4* wp = (const float4*)(wos + k * 96 + cg * 48);
            #pragma unroll
            for (int j = 0; j < 12; j++){
                float4 w = wp[j];
                acc[j].x = fmaf(hk, w.x, acc[j].x);
                acc[j].y = fmaf(hk, w.y, acc[j].y);
                acc[j].z = fmaf(hk, w.z, acc[j].z);
                acc[j].w = fmaf(hk, w.w, acc[j].w);
            }
        }
        float* zp = g_zx + ((size_t)blockIdx.x * 64 + row) * 96 + cg * 48;
        #pragma unroll
        for (int j = 0; j < 12; j++) *(float4*)(zp + j * 4) = acc[j];
    }
}

// =====================================================================
// Outer LSTM + dense head: one warp per batch row; ALL 32 lanes compute.
// Lane l owns gate-cols 3l..3l+2 (scalar fp32: 72 FFMA/step at rt2,
// weights 72 scalar regs -> no spill). h broadcast via double-buffered
// SMEM scalar array (6 LDS.128/lane). Gate exchange via small SMEM
// buffer (3 STS + 4 LDS) so lanes<24 own full units for activations.
// =====================================================================
__device__ __forceinline__ void outer_step_v2(
    float& h, float& c, float z0, float z1, float z2,
    const float4* hb4, float* hw, float* zs, int l,
    const float* w0, const float* w1, const float* w2)
{
    // GEMV: 3 scalar chains over k = 0..23
    #pragma unroll
    for (int j = 0; j < 6; j++){
        float4 hv = hb4[j];                 // h[4j..4j+3]
        z0 = fmaf(hv.x, w0[4*j],     z0);
        z1 = fmaf(hv.x, w1[4*j],     z1);
        z2 = fmaf(hv.x, w2[4*j],     z2);
        z0 = fmaf(hv.y, w0[4*j + 1], z0);
        z1 = fmaf(hv.y, w1[4*j + 1], z1);
        z2 = fmaf(hv.y, w2[4*j + 1], z2);
        z0 = fmaf(hv.z, w0[4*j + 2], z0);
        z1 = fmaf(hv.z, w1[4*j + 2], z1);
        z2 = fmaf(hv.z, w2[4*j + 2], z2);
        z0 = fmaf(hv.w, w0[4*j + 3], z0);
        z1 = fmaf(hv.w, w1[4*j + 3], z1);
        z2 = fmaf(hv.w, w2[4*j + 3], z2);
    }
    // gate exchange
    zs[3*l]     = z0;
    zs[3*l + 1] = z1;
    zs[3*l + 2] = z2;
    __syncwarp();
    if (l < 24){
        float zi = zs[l], zf = zs[24 + l], zg = zs[48 + l], zo = zs[72 + l];
        float fi = sigt(zi), ff = sigt(zf), gg = tanha(zg), oo = sigt(zo);
        c = fmaf(ff, c, fi * gg);
        h = oo * tanha(c);
        hw[l] = h;
    }
    __syncwarp();
}

__global__ void __launch_bounds__(32) outer_kernel(
    const int*   __restrict__ lengths,
    const float* __restrict__ Uo,
    const float* __restrict__ Wd,
    const float* __restrict__ bd,
    float*       __restrict__ out)
{
    __shared__ __align__(16) float hsm[2][24];
    __shared__ __align__(16) float zs[96];

    const int l  = threadIdx.x;
    const int b  = blockIdx.x;
    const int c0 = 3 * l;                  // this lane's 3 gate-cols

    // weights: w*[k] = Uo[k][c0 + *]
    float w0[24], w1[24], w2[24];
    #pragma unroll
    for (int k = 0; k < 24; k++){
        const float* row = Uo + k * 96 + c0;
        w0[k] = __ldg(row);
        w1[k] = __ldg(row + 1);
        w2[k] = __ldg(row + 2);
    }

    const int len = lengths[b];            // in [1, T]
    const float* zr = g_zx + (size_t)b * Tn * 96 + c0;

    // static two-slot prefetch (3 scalars per slot)
    float p00, p01, p02, p10, p11, p12;
    p00 = __ldg(zr); p01 = __ldg(zr + 1); p02 = __ldg(zr + 2);
    {
        const float* z1p = zr + ((len > 1) ? 96 : 0);
        p10 = __ldg(z1p); p11 = __ldg(z1p + 1); p12 = __ldg(z1p + 2);
    }

    if (l < 24) hsm[0][l] = 0.f;
    __syncwarp();

    float h = 0.f, c = 0.f;
    int t = 0;
    while (t < len){
        {   // even step: slot0, read hsm[0] write hsm[1]
            float z0 = p00, z1 = p01, z2 = p02;
            int tp = (t + 2 < len) ? t + 2 : len - 1;
            const float* zq = zr + (size_t)tp * 96;
            p00 = __ldg(zq); p01 = __ldg(zq + 1); p02 = __ldg(zq + 2);
            outer_step_v2(h, c, z0, z1, z2,
                          (const float4*)hsm[0], hsm[1], zs, l, w0, w1, w2);
        }
        if (++t >= len) break;
        {   // odd step: slot1, read hsm[1] write hsm[0]
            float z0 = p10, z1 = p11, z2 = p12;
            int tp = (t + 2 < len) ? t + 2 : len - 1;
            const float* zq = zr + (size_t)tp * 96;
            p10 = __ldg(zq); p11 = __ldg(zq + 1); p12 = __ldg(zq + 2);
            outer_step_v2(h, c, z0, z1, z2,
                          (const float4*)hsm[1], hsm[0], zs, l, w0, w1, w2);
        }
        ++t;
    }

    // dense sigmoid head (h valid in lanes < 24)
    float p = (l < 24) ? h * __ldg(Wd + l) : 0.f;
    #pragma unroll
    for (int off = 16; off; off >>= 1) p += __shfl_xor_sync(0xffffffffu, p, off);
    if (l == 0) out[b] = fmaf(0.5f, tanha(0.5f * (p + bd[0])), 0.5f);
}

extern "C" void kernel_launch(void* const* d_in, const int* in_sizes, int n_in,
                              void* d_out, int out_size)
{
    const float* x       = (const float*)d_in[0];
    const int*   lengths = (const int*)  d_in[1];
    const float* Wi      = (const float*)d_in[2];
    const float* Ui      = (const float*)d_in[3];
    const float* bi      = (const float*)d_in[4];
    const float* Wo      = (const float*)d_in[5];
    const float* Uo      = (const float*)d_in[6];
    const float* bo      = (const float*)d_in[7];
    const float* Wd      = (const float*)d_in[8];
    const float* bd      = (const float*)d_in[9];
    float* out = (float*)d_out;

    cudaFuncSetAttribute(inner_mma,
                         cudaFuncAttributeMaxDynamicSharedMemorySize, SMEM_SZ);

    bprep<<<32, 256>>>(Wi, Ui, bi);
    inner_mma<<<1024, 128, SMEM_SZ>>>(x, Wi, bi, Wo, bo);
    outer_kernel<<<256, 32>>>(lengths, Uo, Wd, bd, out);
}